// round 1
// baseline (speedup 1.0000x reference)
#include <cuda_runtime.h>
#include <cuda_bf16.h>
#include <cstdint>

#define Bv   128
#define Hv   256
#define Tv   2048
#define Vv   32000

#define LOGP_OFF  0
#define HNEW_OFF  (Bv*Vv)                 // 4,096,000
#define ATTN_OFF  (HNEW_OFF + Bv*Hv)      // 4,128,768
#define CTX_OFF   (ATTN_OFF + Bv*Tv)      // 4,390,912

#define NEG_HUGE  (-3.402823466e38f)

// ---------------- scratch (device globals; no allocation allowed) ----------------
__device__ __align__(16) float g_sh[Bv];          // hidden . W_h + attn_b
__device__ __align__(16) float g_cat[Bv * 2 * Hv];// [emb | ctx] per batch
__device__ __align__(16) float g_x[Bv * Hv];      // relu(comb)
__device__ __align__(16) float g_gx[Bv * 3 * Hv];
__device__ __align__(16) float g_gh[Bv * 3 * Hv];
__device__ __align__(16) float g_ht[Hv * Bv];     // h_new transposed [k][b]

// ---------------- f32x2 helpers ----------------
__device__ __forceinline__ unsigned long long ff2(unsigned long long a, unsigned long long b,
                                                  unsigned long long c) {
    unsigned long long d;
    asm("fma.rn.f32x2 %0, %1, %2, %3;" : "=l"(d) : "l"(a), "l"(b), "l"(c));
    return d;
}
__device__ __forceinline__ unsigned long long dup2(float a) {
    unsigned long long d;
    asm("mov.b64 %0, {%1, %1};" : "=l"(d) : "f"(a));
    return d;
}
__device__ __forceinline__ float2 unpk(unsigned long long a) {
    float2 r;
    asm("mov.b64 {%0, %1}, %2;" : "=f"(r.x), "=f"(r.y) : "l"(a));
    return r;
}

// ---------------- K0: embedding gather + hidden score term ----------------
__global__ void k_prep(const int* __restrict__ tokens, const float* __restrict__ hidden,
                       const float* __restrict__ emb_table, const float* __restrict__ attn_W,
                       const float* __restrict__ attn_b) {
    int b = blockIdx.x, tid = threadIdx.x;
    int tok = tokens[b];
    g_cat[b * 512 + tid] = emb_table[(size_t)tok * Hv + tid];
    float v = hidden[b * Hv + tid] * attn_W[tid];   // W_h = attn_W[0:H]
#pragma unroll
    for (int o = 16; o; o >>= 1) v += __shfl_xor_sync(0xffffffffu, v, o);
    __shared__ float sred[8];
    if ((tid & 31) == 0) sred[tid >> 5] = v;
    __syncthreads();
    if (tid == 0) {
        float s = 0.f;
#pragma unroll
        for (int i = 0; i < 8; i++) s += sred[i];
        g_sh[b] = s + attn_b[0];
    }
}

// ---------------- K1: fused attention (single pass over encoder) ----------------
__global__ void __launch_bounds__(512) k_attn(const float* __restrict__ enc,
                                              const float* __restrict__ attn_W,
                                              float* __restrict__ out) {
    int b = blockIdx.x;
    int tid = threadIdx.x, w = tid >> 5, lane = tid & 31;
    __shared__ float s_scores[Tv];
    __shared__ float s_m[16], s_l[16];
    __shared__ __align__(16) float s_ctx[16 * 256];

    int h0 = lane * 8;
    float4 we0 = *(const float4*)(attn_W + Hv + h0);
    float4 we1 = *(const float4*)(attn_W + Hv + h0 + 4);
    float sh = g_sh[b];

    float m0 = NEG_HUGE, l0 = 0.f, m1 = NEG_HUGE, l1 = 0.f;
    float c0[8], c1[8];
#pragma unroll
    for (int j = 0; j < 8; j++) { c0[j] = 0.f; c1[j] = 0.f; }

    const float* base = enc + (size_t)b * Hv + h0;

    for (int t0 = w; t0 < Tv; t0 += 32) {
        int t1 = t0 + 16;
        const float4* p0 = (const float4*)(base + (size_t)t0 * (Bv * Hv));
        const float4* p1 = (const float4*)(base + (size_t)t1 * (Bv * Hv));
        float4 a0 = p0[0], a1 = p0[1];
        float4 b0 = p1[0], b1 = p1[1];

        float ea[8] = {a0.x, a0.y, a0.z, a0.w, a1.x, a1.y, a1.z, a1.w};
        float eb[8] = {b0.x, b0.y, b0.z, b0.w, b1.x, b1.y, b1.z, b1.w};
        float wv[8] = {we0.x, we0.y, we0.z, we0.w, we1.x, we1.y, we1.z, we1.w};

        float s0 = 0.f, s1 = 0.f;
#pragma unroll
        for (int j = 0; j < 8; j++) { s0 += ea[j] * wv[j]; s1 += eb[j] * wv[j]; }
#pragma unroll
        for (int o = 16; o; o >>= 1) {
            s0 += __shfl_xor_sync(0xffffffffu, s0, o);
            s1 += __shfl_xor_sync(0xffffffffu, s1, o);
        }
        s0 += sh; s1 += sh;
        if (lane == 0) { s_scores[t0] = s0; s_scores[t1] = s1; }

        // online softmax chain 0
        {
            float mn = fmaxf(m0, s0);
            float cc = __expf(m0 - mn), p = __expf(s0 - mn);
            l0 = l0 * cc + p;
#pragma unroll
            for (int j = 0; j < 8; j++) c0[j] = c0[j] * cc + p * ea[j];
            m0 = mn;
        }
        // online softmax chain 1
        {
            float mn = fmaxf(m1, s1);
            float cc = __expf(m1 - mn), p = __expf(s1 - mn);
            l1 = l1 * cc + p;
#pragma unroll
            for (int j = 0; j < 8; j++) c1[j] = c1[j] * cc + p * eb[j];
            m1 = mn;
        }
    }

    // merge two chains within warp
    float Mw = fmaxf(m0, m1);
    float e0 = __expf(m0 - Mw), e1 = __expf(m1 - Mw);
    float Lw = l0 * e0 + l1 * e1;
    s_m[w] = Mw; s_l[w] = Lw;
#pragma unroll
    for (int j = 0; j < 8; j++) s_ctx[w * 256 + h0 + j] = c0[j] * e0 + c1[j] * e1;
    __syncthreads();

    float Mg = NEG_HUGE;
#pragma unroll
    for (int i = 0; i < 16; i++) Mg = fmaxf(Mg, s_m[i]);
    float Lg = 0.f;
#pragma unroll
    for (int i = 0; i < 16; i++) Lg += __expf(s_m[i] - Mg) * s_l[i];
    float invL = 1.f / Lg;

    if (tid < 256) {
        float acc = 0.f;
#pragma unroll
        for (int i = 0; i < 16; i++) acc += __expf(s_m[i] - Mg) * s_ctx[i * 256 + tid];
        acc *= invL;
        out[CTX_OFF + b * Hv + tid] = acc;
        g_cat[b * 512 + 256 + tid] = acc;
    }
    for (int t = tid; t < Tv; t += 512)
        out[ATTN_OFF + (size_t)b * Tv + t] = __expf(s_scores[t] - Mg) * invL;
}

// ---------------- K2: small linear Y[b,n] = act(X[b,:] . W[n,:] + bias[n]) ----------------
template <int K, bool RELU>
__global__ void __launch_bounds__(256) k_linear(const float* __restrict__ X,
                                                const float* __restrict__ W,
                                                const float* __restrict__ bias,
                                                float* __restrict__ Y, int N) {
    __shared__ __align__(16) float xs[8][K];
    int bb0 = blockIdx.y * 8;
    for (int idx = threadIdx.x; idx < 8 * K; idx += 256)
        xs[idx / K][idx % K] = X[(size_t)(bb0 + idx / K) * K + (idx % K)];
    __syncthreads();

    int n = blockIdx.x * 256 + threadIdx.x;
    const float4* wr4 = (const float4*)(W + (size_t)n * K);
    float acc[8];
#pragma unroll
    for (int bb = 0; bb < 8; bb++) acc[bb] = 0.f;

#pragma unroll 4
    for (int k4 = 0; k4 < K / 4; k4++) {
        float4 wv = wr4[k4];
        int k = k4 * 4;
#pragma unroll
        for (int bb = 0; bb < 8; bb++) {
            float4 xv = *(const float4*)&xs[bb][k];
            acc[bb] += wv.x * xv.x + wv.y * xv.y + wv.z * xv.z + wv.w * xv.w;
        }
    }
    float bvl = bias[n];
#pragma unroll
    for (int bb = 0; bb < 8; bb++) {
        float r = acc[bb] + bvl;
        if (RELU) r = fmaxf(r, 0.f);
        Y[(size_t)(bb0 + bb) * N + n] = r;
    }
}

// ---------------- K2c: GRU elementwise + h transpose ----------------
__global__ void k_gru(const float* __restrict__ hidden, float* __restrict__ out) {
    int b = blockIdx.x, h = threadIdx.x;
    float xr = g_gx[b * 768 + h],        hr = g_gh[b * 768 + h];
    float xz = g_gx[b * 768 + 256 + h],  hz = g_gh[b * 768 + 256 + h];
    float xn = g_gx[b * 768 + 512 + h],  hn = g_gh[b * 768 + 512 + h];
    float r = 1.f / (1.f + __expf(-(xr + hr)));
    float z = 1.f / (1.f + __expf(-(xz + hz)));
    float n = tanhf(xn + r * hn);
    float hprev = hidden[b * Hv + h];
    float hnew = (1.f - z) * n + z * hprev;
    out[HNEW_OFF + b * Hv + h] = hnew;
    g_ht[h * Bv + b] = hnew;
}

// ---------------- K3: logits GEMM (f32x2 packed FMA) ----------------
// block tile: 64 vocab x 128 batch, k chunked by 32, 3 blocks/SM
__global__ void __launch_bounds__(256, 3) k_logits(const float* __restrict__ Wv,
                                                   const float* __restrict__ out_b,
                                                   float* __restrict__ out) {
    __shared__ __align__(16) float s_wt[32 * 68];   // [k][v] padded stride 68
    __shared__ __align__(16) float s_ht[32 * 128];  // [k][b]
    int tid = threadIdx.x;
    int vb = blockIdx.x * 64;
    int vi = (tid & 15) * 4;
    int bg = (tid >> 4) * 8;

    unsigned long long acc[16];
#pragma unroll
    for (int i = 0; i < 16; i++) acc[i] = 0ull;

    for (int kc = 0; kc < 256; kc += 32) {
        __syncthreads();
#pragma unroll
        for (int i = 0; i < 8; i++) {               // 64*32 / 256
            int idx = i * 256 + tid;
            int v = idx >> 5, k = idx & 31;
            s_wt[k * 68 + v] = Wv[(size_t)(vb + v) * 256 + kc + k];
        }
#pragma unroll
        for (int i = 0; i < 16; i++) {              // 32*128 / 256
            int idx = i * 256 + tid;
            int k = idx >> 7, bb = idx & 127;
            s_ht[idx] = g_ht[(kc + k) * 128 + bb];
        }
        __syncthreads();

#pragma unroll 4
        for (int k = 0; k < 32; k++) {
            float4 w4 = *(const float4*)&s_wt[k * 68 + vi];
            ulonglong2 hA = *(const ulonglong2*)&s_ht[k * 128 + bg];
            ulonglong2 hB = *(const ulonglong2*)&s_ht[k * 128 + bg + 4];
            unsigned long long w0 = dup2(w4.x), w1 = dup2(w4.y);
            unsigned long long w2 = dup2(w4.z), w3 = dup2(w4.w);
            acc[0]  = ff2(w0, hA.x, acc[0]);  acc[1]  = ff2(w0, hA.y, acc[1]);
            acc[2]  = ff2(w0, hB.x, acc[2]);  acc[3]  = ff2(w0, hB.y, acc[3]);
            acc[4]  = ff2(w1, hA.x, acc[4]);  acc[5]  = ff2(w1, hA.y, acc[5]);
            acc[6]  = ff2(w1, hB.x, acc[6]);  acc[7]  = ff2(w1, hB.y, acc[7]);
            acc[8]  = ff2(w2, hA.x, acc[8]);  acc[9]  = ff2(w2, hA.y, acc[9]);
            acc[10] = ff2(w2, hB.x, acc[10]); acc[11] = ff2(w2, hB.y, acc[11]);
            acc[12] = ff2(w3, hA.x, acc[12]); acc[13] = ff2(w3, hA.y, acc[13]);
            acc[14] = ff2(w3, hB.x, acc[14]); acc[15] = ff2(w3, hB.y, acc[15]);
        }
    }

    // epilogue: stage to smem in 2 halves for coalesced global stores
    float* res = s_ht;   // reuse (4096 floats = 64 b-rows x 64 v)
    for (int half = 0; half < 2; half++) {
        __syncthreads();
        if ((bg >= 64) == (half == 1)) {
            int bl = bg - half * 64;
#pragma unroll
            for (int v = 0; v < 4; v++)
#pragma unroll
                for (int p = 0; p < 4; p++) {
                    float2 f = unpk(acc[v * 4 + p]);
                    res[(bl + 2 * p) * 64 + vi + v] = f.x;
                    res[(bl + 2 * p + 1) * 64 + vi + v] = f.y;
                }
        }
        __syncthreads();
#pragma unroll
        for (int i = 0; i < 16; i++) {              // 64*64 / 256
            int idx = i * 256 + tid;
            int bb = idx >> 6, v = idx & 63;
            out[(size_t)(half * 64 + bb) * Vv + vb + v] = res[idx] + out_b[vb + v];
        }
    }
}

// ---------------- K4: log_softmax in place over vocab ----------------
__global__ void __launch_bounds__(1024) k_logsoftmax(float* __restrict__ out) {
    int b = blockIdx.x, tid = threadIdx.x;
    float* row = out + (size_t)b * Vv;
    float m = NEG_HUGE, l = 0.f;
    for (int v = tid; v < Vv; v += 1024) {
        float x = row[v];
        float mn = fmaxf(m, x);
        l = l * __expf(m - mn) + __expf(x - mn);
        m = mn;
    }
#pragma unroll
    for (int o = 16; o; o >>= 1) {
        float m2 = __shfl_xor_sync(0xffffffffu, m, o);
        float l2 = __shfl_xor_sync(0xffffffffu, l, o);
        float mn = fmaxf(m, m2);
        l = l * __expf(m - mn) + l2 * __expf(m2 - mn);
        m = mn;
    }
    __shared__ float sm[32], sl[32];
    if ((tid & 31) == 0) { sm[tid >> 5] = m; sl[tid >> 5] = l; }
    __syncthreads();
    float M = NEG_HUGE;
#pragma unroll
    for (int i = 0; i < 32; i++) M = fmaxf(M, sm[i]);
    float L = 0.f;
#pragma unroll
    for (int i = 0; i < 32; i++) L += sl[i] * __expf(sm[i] - M);
    float lse = M + logf(L);
    for (int v = tid; v < Vv; v += 1024) row[v] -= lse;
}

// ---------------- launch ----------------
extern "C" void kernel_launch(void* const* d_in, const int* in_sizes, int n_in,
                              void* d_out, int out_size) {
    const int*   tokens    = (const int*)d_in[0];
    const float* hidden    = (const float*)d_in[1];
    const float* enc       = (const float*)d_in[2];
    const float* emb_table = (const float*)d_in[3];
    const float* attn_W    = (const float*)d_in[4];
    const float* attn_b    = (const float*)d_in[5];
    const float* comb_W    = (const float*)d_in[6];
    const float* comb_b    = (const float*)d_in[7];
    const float* gru_Wih   = (const float*)d_in[8];
    const float* gru_Whh   = (const float*)d_in[9];
    const float* gru_bih   = (const float*)d_in[10];
    const float* gru_bhh   = (const float*)d_in[11];
    const float* out_W     = (const float*)d_in[12];
    const float* out_b     = (const float*)d_in[13];
    float* out = (float*)d_out;

    void *p_cat, *p_x, *p_gx, *p_gh;
    cudaGetSymbolAddress(&p_cat, g_cat);
    cudaGetSymbolAddress(&p_x, g_x);
    cudaGetSymbolAddress(&p_gx, g_gx);
    cudaGetSymbolAddress(&p_gh, g_gh);

    k_prep<<<Bv, 256>>>(tokens, hidden, emb_table, attn_W, attn_b);
    k_attn<<<Bv, 512>>>(enc, attn_W, out);
    k_linear<512, true ><<<dim3(1, 16), 256>>>((const float*)p_cat, comb_W, comb_b,
                                               (float*)p_x, 256);
    k_linear<256, false><<<dim3(3, 16), 256>>>((const float*)p_x, gru_Wih, gru_bih,
                                               (float*)p_gx, 768);
    k_linear<256, false><<<dim3(3, 16), 256>>>(hidden, gru_Whh, gru_bhh,
                                               (float*)p_gh, 768);
    k_gru<<<Bv, 256>>>(hidden, out);
    k_logits<<<500, 256>>>(out_W, out_b, out);
    k_logsoftmax<<<Bv, 1024>>>(out);
}

// round 2
// speedup vs baseline: 1.3942x; 1.3942x over previous
#include <cuda_runtime.h>
#include <cuda_bf16.h>
#include <cstdint>

#define Bv   128
#define Hv   256
#define Tv   2048
#define Vv   32000
#define NTILES 500            // Vv / 64

#define LOGP_OFF  0
#define HNEW_OFF  (Bv*Vv)                 // 4,096,000
#define ATTN_OFF  (HNEW_OFF + Bv*Hv)      // 4,128,768
#define CTX_OFF   (ATTN_OFF + Bv*Tv)      // 4,390,912

#define NEG_HUGE  (-3.402823466e38f)

// ---------------- scratch (device globals; no allocation allowed) ----------------
__device__ __align__(16) float g_x[Bv * Hv];      // relu(comb)
__device__ __align__(16) float g_gx[Bv * 3 * Hv];
__device__ __align__(16) float g_gh[Bv * 3 * Hv];
__device__ __align__(16) float g_ht[Hv * Bv];     // h_new transposed [k][b]
__device__ __align__(16) float g_pmax[NTILES * Bv];
__device__ __align__(16) float g_psum[NTILES * Bv];

// ---------------- f32x2 helpers ----------------
__device__ __forceinline__ unsigned long long ff2(unsigned long long a, unsigned long long b,
                                                  unsigned long long c) {
    unsigned long long d;
    asm("fma.rn.f32x2 %0, %1, %2, %3;" : "=l"(d) : "l"(a), "l"(b), "l"(c));
    return d;
}
__device__ __forceinline__ unsigned long long dup2(float a) {
    unsigned long long d;
    asm("mov.b64 %0, {%1, %1};" : "=l"(d) : "f"(a));
    return d;
}
__device__ __forceinline__ float2 unpk(unsigned long long a) {
    float2 r;
    asm("mov.b64 {%0, %1}, %2;" : "=f"(r.x), "=f"(r.y) : "l"(a));
    return r;
}

// ---------------- K1: fused attention (single pass over encoder) ----------------
__global__ void __launch_bounds__(512) k_attn(const float* __restrict__ enc,
                                              const float* __restrict__ attn_W,
                                              const float* __restrict__ hidden,
                                              const float* __restrict__ attn_b,
                                              float* __restrict__ out) {
    int b = blockIdx.x;
    int tid = threadIdx.x, w = tid >> 5, lane = tid & 31;
    __shared__ float s_scores[Tv];
    __shared__ float s_m[16], s_l[16];
    __shared__ __align__(16) float s_ctx[16 * 256];
    __shared__ float s_shred[8];

    // hidden . W_h + attn_b  (scalar per batch)
    float hv = 0.f;
    if (tid < 256) hv = hidden[b * Hv + tid] * attn_W[tid];
#pragma unroll
    for (int o = 16; o; o >>= 1) hv += __shfl_xor_sync(0xffffffffu, hv, o);
    if (lane == 0 && w < 8) s_shred[w] = hv;
    __syncthreads();
    float sh = attn_b[0];
#pragma unroll
    for (int i = 0; i < 8; i++) sh += s_shred[i];

    int h0 = lane * 8;
    float4 we0 = *(const float4*)(attn_W + Hv + h0);
    float4 we1 = *(const float4*)(attn_W + Hv + h0 + 4);

    float m0 = NEG_HUGE, l0 = 0.f, m1 = NEG_HUGE, l1 = 0.f;
    float c0[8], c1[8];
#pragma unroll
    for (int j = 0; j < 8; j++) { c0[j] = 0.f; c1[j] = 0.f; }

    const float* base = enc + (size_t)b * Hv + h0;
    const size_t STR = (size_t)Bv * Hv;

    // software-pipelined loads
    float4 A0, A1, B0, B1;
    {
        const float4* p0 = (const float4*)(base + (size_t)w * STR);
        const float4* p1 = (const float4*)(base + (size_t)(w + 16) * STR);
        A0 = p0[0]; A1 = p0[1]; B0 = p1[0]; B1 = p1[1];
    }

    for (int t0 = w; t0 < Tv; t0 += 32) {
        float4 a0 = A0, a1 = A1, b0 = B0, b1 = B1;
        int tn = t0 + 32;
        if (tn < Tv) {
            const float4* p0 = (const float4*)(base + (size_t)tn * STR);
            const float4* p1 = (const float4*)(base + (size_t)(tn + 16) * STR);
            A0 = p0[0]; A1 = p0[1]; B0 = p1[0]; B1 = p1[1];
        }

        float ea[8] = {a0.x, a0.y, a0.z, a0.w, a1.x, a1.y, a1.z, a1.w};
        float eb[8] = {b0.x, b0.y, b0.z, b0.w, b1.x, b1.y, b1.z, b1.w};
        float wv[8] = {we0.x, we0.y, we0.z, we0.w, we1.x, we1.y, we1.z, we1.w};

        float s0 = 0.f, s1 = 0.f;
#pragma unroll
        for (int j = 0; j < 8; j++) { s0 += ea[j] * wv[j]; s1 += eb[j] * wv[j]; }
#pragma unroll
        for (int o = 16; o; o >>= 1) {
            s0 += __shfl_xor_sync(0xffffffffu, s0, o);
            s1 += __shfl_xor_sync(0xffffffffu, s1, o);
        }
        s0 += sh; s1 += sh;
        if (lane == 0) { s_scores[t0] = s0; s_scores[t0 + 16] = s1; }

        {
            float mn = fmaxf(m0, s0);
            float cc = __expf(m0 - mn), p = __expf(s0 - mn);
            l0 = l0 * cc + p;
#pragma unroll
            for (int j = 0; j < 8; j++) c0[j] = c0[j] * cc + p * ea[j];
            m0 = mn;
        }
        {
            float mn = fmaxf(m1, s1);
            float cc = __expf(m1 - mn), p = __expf(s1 - mn);
            l1 = l1 * cc + p;
#pragma unroll
            for (int j = 0; j < 8; j++) c1[j] = c1[j] * cc + p * eb[j];
            m1 = mn;
        }
    }

    // merge two chains within warp
    float Mw = fmaxf(m0, m1);
    float e0 = __expf(m0 - Mw), e1 = __expf(m1 - Mw);
    float Lw = l0 * e0 + l1 * e1;
    s_m[w] = Mw; s_l[w] = Lw;
#pragma unroll
    for (int j = 0; j < 8; j++) s_ctx[w * 256 + h0 + j] = c0[j] * e0 + c1[j] * e1;
    __syncthreads();

    float Mg = NEG_HUGE;
#pragma unroll
    for (int i = 0; i < 16; i++) Mg = fmaxf(Mg, s_m[i]);
    float Lg = 0.f;
#pragma unroll
    for (int i = 0; i < 16; i++) Lg += __expf(s_m[i] - Mg) * s_l[i];
    float invL = 1.f / Lg;

    if (tid < 256) {
        float acc = 0.f;
#pragma unroll
        for (int i = 0; i < 16; i++) acc += __expf(s_m[i] - Mg) * s_ctx[i * 256 + tid];
        acc *= invL;
        out[CTX_OFF + b * Hv + tid] = acc;
    }
    for (int t = tid; t < Tv; t += 512)
        out[ATTN_OFF + (size_t)b * Tv + t] = __expf(s_scores[t] - Mg) * invL;
}

// ---------------- K2a: comb linear (X = [emb | ctx]) ----------------
// grid (N/8=32, B/16=8), block 256 = 8 warps; warp owns one n over 16 b.
__global__ void __launch_bounds__(256) k_comb(const int* __restrict__ tokens,
                                              const float* __restrict__ emb_table,
                                              const float* __restrict__ comb_W,
                                              const float* __restrict__ comb_b,
                                              const float* __restrict__ out) {
    __shared__ __align__(16) float xs[16][512];
    int tid = threadIdx.x, w = tid >> 5, lane = tid & 31;
    int b0 = blockIdx.y * 16;
    const float* ctx = out + CTX_OFF;

    for (int idx = tid; idx < 16 * 512; idx += 256) {
        int bb = idx >> 9, k = idx & 511;
        int gb = b0 + bb;
        float v;
        if (k < 256) {
            int tok = tokens[gb];
            v = emb_table[(size_t)tok * Hv + k];
        } else {
            v = ctx[gb * Hv + (k - 256)];
        }
        xs[bb][k] = v;
    }
    __syncthreads();

    int n = blockIdx.x * 8 + w;
    const float* wr = comb_W + (size_t)n * 512 + lane * 4;
    float4 w0 = *(const float4*)(wr);
    float4 w1 = *(const float4*)(wr + 128);
    float4 w2 = *(const float4*)(wr + 256);
    float4 w3 = *(const float4*)(wr + 384);
    float bvl = comb_b[n];

#pragma unroll 4
    for (int bb = 0; bb < 16; bb++) {
        const float* xr = &xs[bb][lane * 4];
        float4 x0 = *(const float4*)(xr);
        float4 x1 = *(const float4*)(xr + 128);
        float4 x2 = *(const float4*)(xr + 256);
        float4 x3 = *(const float4*)(xr + 384);
        float p = w0.x * x0.x + w0.y * x0.y + w0.z * x0.z + w0.w * x0.w
                + w1.x * x1.x + w1.y * x1.y + w1.z * x1.z + w1.w * x1.w
                + w2.x * x2.x + w2.y * x2.y + w2.z * x2.z + w2.w * x2.w
                + w3.x * x3.x + w3.y * x3.y + w3.z * x3.z + w3.w * x3.w;
#pragma unroll
        for (int o = 16; o; o >>= 1) p += __shfl_xor_sync(0xffffffffu, p, o);
        if (lane == 0) g_x[(b0 + bb) * Hv + n] = fmaxf(p + bvl, 0.f);
    }
}

// ---------------- K2b: gx and gh in one launch ----------------
// grid (768/8=96, B/32=4, 2), block 256; z=0: gx = g_x@Wih^T, z=1: gh = hidden@Whh^T
__global__ void __launch_bounds__(256) k_gxgh(const float* __restrict__ hidden,
                                              const float* __restrict__ Wih,
                                              const float* __restrict__ Whh,
                                              const float* __restrict__ bih,
                                              const float* __restrict__ bhh) {
    __shared__ __align__(16) float xs[32][256];
    int tid = threadIdx.x, w = tid >> 5, lane = tid & 31;
    int b0 = blockIdx.y * 32;
    int z = blockIdx.z;
    const float* X = z ? hidden : g_x;
    const float* W = z ? Whh : Wih;
    const float* bias = z ? bhh : bih;
    float* Y = z ? g_gh : g_gx;

    for (int idx = tid; idx < 32 * 256; idx += 256)
        xs[idx >> 8][idx & 255] = X[(size_t)b0 * Hv + idx];
    __syncthreads();

    int n = blockIdx.x * 8 + w;
    const float* wr = W + (size_t)n * 256 + lane * 4;
    float4 w0 = *(const float4*)(wr);
    float4 w1 = *(const float4*)(wr + 128);
    float bvl = bias[n];

#pragma unroll 4
    for (int bb = 0; bb < 32; bb++) {
        const float* xr = &xs[bb][lane * 4];
        float4 x0 = *(const float4*)(xr);
        float4 x1 = *(const float4*)(xr + 128);
        float p = w0.x * x0.x + w0.y * x0.y + w0.z * x0.z + w0.w * x0.w
                + w1.x * x1.x + w1.y * x1.y + w1.z * x1.z + w1.w * x1.w;
#pragma unroll
        for (int o = 16; o; o >>= 1) p += __shfl_xor_sync(0xffffffffu, p, o);
        if (lane == 0) Y[(b0 + bb) * 768 + n] = p + bvl;
    }
}

// ---------------- K2c: GRU elementwise + h transpose ----------------
__global__ void k_gru(const float* __restrict__ hidden, float* __restrict__ out) {
    int b = blockIdx.x, h = threadIdx.x;
    float xr = g_gx[b * 768 + h],        hr = g_gh[b * 768 + h];
    float xz = g_gx[b * 768 + 256 + h],  hz = g_gh[b * 768 + 256 + h];
    float xn = g_gx[b * 768 + 512 + h],  hn = g_gh[b * 768 + 512 + h];
    float r = 1.f / (1.f + __expf(-(xr + hr)));
    float z = 1.f / (1.f + __expf(-(xz + hz)));
    float n = tanhf(xn + r * hn);
    float hprev = hidden[b * Hv + h];
    float hnew = (1.f - z) * n + z * hprev;
    out[HNEW_OFF + b * Hv + h] = hnew;
    g_ht[h * Bv + b] = hnew;
}

// ---------------- K3: logits GEMM (f32x2) + per-tile softmax partials ----------------
__global__ void __launch_bounds__(256, 3) k_logits(const float* __restrict__ Wv,
                                                   const float* __restrict__ out_b,
                                                   float* __restrict__ out) {
    __shared__ __align__(16) float s_wt[32 * 68];   // [k][v] padded stride 68
    __shared__ __align__(16) float s_ht[32 * 128];  // [k][b]
    int tid = threadIdx.x, w = tid >> 5, lane = tid & 31;
    int vb = blockIdx.x * 64;
    int vi = (tid & 15) * 4;
    int bg = (tid >> 4) * 8;

    unsigned long long acc[16];
#pragma unroll
    for (int i = 0; i < 16; i++) acc[i] = 0ull;

    for (int kc = 0; kc < 256; kc += 32) {
        __syncthreads();
#pragma unroll
        for (int i = 0; i < 8; i++) {
            int idx = i * 256 + tid;
            int v = idx >> 5, k = idx & 31;
            s_wt[k * 68 + v] = Wv[(size_t)(vb + v) * 256 + kc + k];
        }
#pragma unroll
        for (int i = 0; i < 16; i++) {
            int idx = i * 256 + tid;
            s_ht[idx] = g_ht[kc * 128 + idx];
        }
        __syncthreads();

#pragma unroll 4
        for (int k = 0; k < 32; k++) {
            float4 w4 = *(const float4*)&s_wt[k * 68 + vi];
            ulonglong2 hA = *(const ulonglong2*)&s_ht[k * 128 + bg];
            ulonglong2 hB = *(const ulonglong2*)&s_ht[k * 128 + bg + 4];
            unsigned long long w0 = dup2(w4.x), w1 = dup2(w4.y);
            unsigned long long w2 = dup2(w4.z), w3 = dup2(w4.w);
            acc[0]  = ff2(w0, hA.x, acc[0]);  acc[1]  = ff2(w0, hA.y, acc[1]);
            acc[2]  = ff2(w0, hB.x, acc[2]);  acc[3]  = ff2(w0, hB.y, acc[3]);
            acc[4]  = ff2(w1, hA.x, acc[4]);  acc[5]  = ff2(w1, hA.y, acc[5]);
            acc[6]  = ff2(w1, hB.x, acc[6]);  acc[7]  = ff2(w1, hB.y, acc[7]);
            acc[8]  = ff2(w2, hA.x, acc[8]);  acc[9]  = ff2(w2, hA.y, acc[9]);
            acc[10] = ff2(w2, hB.x, acc[10]); acc[11] = ff2(w2, hB.y, acc[11]);
            acc[12] = ff2(w3, hA.x, acc[12]); acc[13] = ff2(w3, hA.y, acc[13]);
            acc[14] = ff2(w3, hB.x, acc[14]); acc[15] = ff2(w3, hB.y, acc[15]);
        }
    }

    float bv0 = out_b[vb + lane];
    float bv1 = out_b[vb + 32 + lane];

    float* res = s_ht;   // reuse (64 b-rows x 64 v)
    for (int half = 0; half < 2; half++) {
        __syncthreads();
        if ((bg >= 64) == (half == 1)) {
            int bl = bg - half * 64;
#pragma unroll
            for (int v = 0; v < 4; v++)
#pragma unroll
                for (int p = 0; p < 4; p++) {
                    float2 f = unpk(acc[v * 4 + p]);
                    res[(bl + 2 * p) * 64 + vi + v] = f.x;
                    res[(bl + 2 * p + 1) * 64 + vi + v] = f.y;
                }
        }
        __syncthreads();
#pragma unroll
        for (int i = 0; i < 16; i++) {
            int idx = i * 256 + tid;
            int bb = idx >> 6, v = idx & 63;
            out[(size_t)(half * 64 + bb) * Vv + vb + v] = res[idx] + out_b[vb + v];
        }
        // per-row max / sumexp partials for log_softmax
#pragma unroll
        for (int r0 = 0; r0 < 8; r0++) {
            int r = r0 * 8 + w;
            float x0 = res[r * 64 + lane] + bv0;
            float x1 = res[r * 64 + 32 + lane] + bv1;
            float mx = fmaxf(x0, x1);
#pragma unroll
            for (int o = 16; o; o >>= 1) mx = fmaxf(mx, __shfl_xor_sync(0xffffffffu, mx, o));
            float se = __expf(x0 - mx) + __expf(x1 - mx);
#pragma unroll
            for (int o = 16; o; o >>= 1) se += __shfl_xor_sync(0xffffffffu, se, o);
            if (lane == 0) {
                int gb = half * 64 + r;
                g_pmax[blockIdx.x * Bv + gb] = mx;
                g_psum[blockIdx.x * Bv + gb] = se;
            }
        }
    }
}

// ---------------- K4: log_softmax finalize ----------------
__global__ void __launch_bounds__(512) k_lsm(float* __restrict__ out) {
    int b = blockIdx.x, tid = threadIdx.x, w = tid >> 5, lane = tid & 31;
    float m = NEG_HUGE, l = 0.f;
    for (int i = tid; i < NTILES; i += 512) {
        float mx = g_pmax[i * Bv + b];
        float se = g_psum[i * Bv + b];
        float nm = fmaxf(m, mx);
        l = l * __expf(m - nm) + se * __expf(mx - nm);
        m = nm;
    }
#pragma unroll
    for (int o = 16; o; o >>= 1) {
        float m2 = __shfl_xor_sync(0xffffffffu, m, o);
        float l2 = __shfl_xor_sync(0xffffffffu, l, o);
        float nm = fmaxf(m, m2);
        l = l * __expf(m - nm) + l2 * __expf(m2 - nm);
        m = nm;
    }
    __shared__ float sm[16], sl[16];
    if (lane == 0) { sm[w] = m; sl[w] = l; }
    __syncthreads();
    float M = NEG_HUGE;
#pragma unroll
    for (int i = 0; i < 16; i++) M = fmaxf(M, sm[i]);
    float L = 0.f;
#pragma unroll
    for (int i = 0; i < 16; i++) L += sl[i] * __expf(sm[i] - M);
    float lse = M + logf(L);

    float* row = out + (size_t)b * Vv;
    for (int v = tid; v < Vv; v += 512) row[v] -= lse;
}

// ---------------- launch ----------------
extern "C" void kernel_launch(void* const* d_in, const int* in_sizes, int n_in,
                              void* d_out, int out_size) {
    const int*   tokens    = (const int*)d_in[0];
    const float* hidden    = (const float*)d_in[1];
    const float* enc       = (const float*)d_in[2];
    const float* emb_table = (const float*)d_in[3];
    const float* attn_W    = (const float*)d_in[4];
    const float* attn_b    = (const float*)d_in[5];
    const float* comb_W    = (const float*)d_in[6];
    const float* comb_b    = (const float*)d_in[7];
    const float* gru_Wih   = (const float*)d_in[8];
    const float* gru_Whh   = (const float*)d_in[9];
    const float* gru_bih   = (const float*)d_in[10];
    const float* gru_bhh   = (const float*)d_in[11];
    const float* out_W     = (const float*)d_in[12];
    const float* out_b     = (const float*)d_in[13];
    float* out = (float*)d_out;

    k_attn<<<Bv, 512>>>(enc, attn_W, hidden, attn_b, out);
    k_comb<<<dim3(32, 8), 256>>>(tokens, emb_table, comb_W, comb_b, out);
    k_gxgh<<<dim3(96, 4, 2), 256>>>(hidden, gru_Wih, gru_Whh, gru_bih, gru_bhh);
    k_gru<<<Bv, 256>>>(hidden, out);
    k_logits<<<NTILES, 256>>>(out_W, out_b, out);
    k_lsm<<<Bv, 512>>>(out);
}

// round 3
// speedup vs baseline: 1.8204x; 1.3056x over previous
#include <cuda_runtime.h>
#include <cuda_bf16.h>
#include <cstdint>

#define Bv   128
#define Hv   256
#define Tv   2048
#define Vv   32000
#define NTILES 250            // Vv / 128

#define LOGP_OFF  0
#define HNEW_OFF  (Bv*Vv)                 // 4,096,000
#define ATTN_OFF  (HNEW_OFF + Bv*Hv)      // 4,128,768
#define CTX_OFF   (ATTN_OFF + Bv*Tv)      // 4,390,912

#define NEG_HUGE  (-3.402823466e38f)

// ---------------- scratch ----------------
__device__ __align__(16) float g_x[Bv * Hv];
__device__ __align__(16) float g_gx[Bv * 3 * Hv];
__device__ __align__(16) float g_gh[Bv * 3 * Hv];
__device__ __align__(16) float g_ht[Hv * Bv];     // h_new transposed [k][b]
__device__ __align__(16) float g_pmax[NTILES * Bv];
__device__ __align__(16) float g_psum[NTILES * Bv];

// ---------------- helpers ----------------
__device__ __forceinline__ uint32_t to_tf32(float x) {
    uint32_t r;
    asm("cvt.rna.tf32.f32 %0, %1;" : "=r"(r) : "f"(x));
    return r;
}
__device__ __forceinline__ void mma_tf32(float* c, uint32_t a0, uint32_t a1,
                                         uint32_t a2, uint32_t a3,
                                         uint32_t b0, uint32_t b1) {
    asm("mma.sync.aligned.m16n8k8.row.col.f32.tf32.tf32.f32 "
        "{%0,%1,%2,%3},{%4,%5,%6,%7},{%8,%9},{%0,%1,%2,%3};"
        : "+f"(c[0]), "+f"(c[1]), "+f"(c[2]), "+f"(c[3])
        : "r"(a0), "r"(a1), "r"(a2), "r"(a3), "r"(b0), "r"(b1));
}
__device__ __forceinline__ float tanh_fast(float x) {
    float r;
    asm("tanh.approx.f32 %0, %1;" : "=f"(r) : "f"(x));
    return r;
}

// ---------------- K1: fused attention (single pass over encoder) ----------------
__global__ void __launch_bounds__(512) k_attn(const float* __restrict__ enc,
                                              const float* __restrict__ attn_W,
                                              const float* __restrict__ hidden,
                                              const float* __restrict__ attn_b,
                                              float* __restrict__ out) {
    int b = blockIdx.x;
    int tid = threadIdx.x, w = tid >> 5, lane = tid & 31;
    __shared__ float s_scores[Tv];
    __shared__ float s_m[16], s_l[16];
    __shared__ __align__(16) float s_ctx[16 * 256];
    __shared__ float s_shred[8];

    float hv = 0.f;
    if (tid < 256) hv = hidden[b * Hv + tid] * attn_W[tid];
#pragma unroll
    for (int o = 16; o; o >>= 1) hv += __shfl_xor_sync(0xffffffffu, hv, o);
    if (lane == 0 && w < 8) s_shred[w] = hv;
    __syncthreads();
    float sh = attn_b[0];
#pragma unroll
    for (int i = 0; i < 8; i++) sh += s_shred[i];

    int h0 = lane * 8;
    float4 we0 = *(const float4*)(attn_W + Hv + h0);
    float4 we1 = *(const float4*)(attn_W + Hv + h0 + 4);

    float m0 = NEG_HUGE, l0 = 0.f, m1 = NEG_HUGE, l1 = 0.f;
    float c0[8], c1[8];
#pragma unroll
    for (int j = 0; j < 8; j++) { c0[j] = 0.f; c1[j] = 0.f; }

    const float* base = enc + (size_t)b * Hv + h0;
    const size_t STR = (size_t)Bv * Hv;

    float4 A0, A1, B0, B1;
    {
        const float4* p0 = (const float4*)(base + (size_t)w * STR);
        const float4* p1 = (const float4*)(base + (size_t)(w + 16) * STR);
        A0 = p0[0]; A1 = p0[1]; B0 = p1[0]; B1 = p1[1];
    }

    for (int t0 = w; t0 < Tv; t0 += 32) {
        float4 a0 = A0, a1 = A1, b0 = B0, b1 = B1;
        int tn = t0 + 32;
        if (tn < Tv) {
            const float4* p0 = (const float4*)(base + (size_t)tn * STR);
            const float4* p1 = (const float4*)(base + (size_t)(tn + 16) * STR);
            A0 = p0[0]; A1 = p0[1]; B0 = p1[0]; B1 = p1[1];
        }

        float ea[8] = {a0.x, a0.y, a0.z, a0.w, a1.x, a1.y, a1.z, a1.w};
        float eb[8] = {b0.x, b0.y, b0.z, b0.w, b1.x, b1.y, b1.z, b1.w};
        float wv[8] = {we0.x, we0.y, we0.z, we0.w, we1.x, we1.y, we1.z, we1.w};

        float s0 = 0.f, s1 = 0.f;
#pragma unroll
        for (int j = 0; j < 8; j++) { s0 += ea[j] * wv[j]; s1 += eb[j] * wv[j]; }
#pragma unroll
        for (int o = 16; o; o >>= 1) {
            s0 += __shfl_xor_sync(0xffffffffu, s0, o);
            s1 += __shfl_xor_sync(0xffffffffu, s1, o);
        }
        s0 += sh; s1 += sh;
        if (lane == 0) { s_scores[t0] = s0; s_scores[t0 + 16] = s1; }

        {
            float mn = fmaxf(m0, s0);
            float cc = __expf(m0 - mn), p = __expf(s0 - mn);
            l0 = l0 * cc + p;
#pragma unroll
            for (int j = 0; j < 8; j++) c0[j] = c0[j] * cc + p * ea[j];
            m0 = mn;
        }
        {
            float mn = fmaxf(m1, s1);
            float cc = __expf(m1 - mn), p = __expf(s1 - mn);
            l1 = l1 * cc + p;
#pragma unroll
            for (int j = 0; j < 8; j++) c1[j] = c1[j] * cc + p * eb[j];
            m1 = mn;
        }
    }

    float Mw = fmaxf(m0, m1);
    float e0 = __expf(m0 - Mw), e1 = __expf(m1 - Mw);
    float Lw = l0 * e0 + l1 * e1;
    s_m[w] = Mw; s_l[w] = Lw;
#pragma unroll
    for (int j = 0; j < 8; j++) s_ctx[w * 256 + h0 + j] = c0[j] * e0 + c1[j] * e1;
    __syncthreads();

    float Mg = NEG_HUGE;
#pragma unroll
    for (int i = 0; i < 16; i++) Mg = fmaxf(Mg, s_m[i]);
    float Lg = 0.f;
#pragma unroll
    for (int i = 0; i < 16; i++) Lg += __expf(s_m[i] - Mg) * s_l[i];
    float invL = 1.f / Lg;

    if (tid < 256) {
        float acc = 0.f;
#pragma unroll
        for (int i = 0; i < 16; i++) acc += __expf(s_m[i] - Mg) * s_ctx[i * 256 + tid];
        acc *= invL;
        out[CTX_OFF + b * Hv + tid] = acc;
    }
    for (int t = tid; t < Tv; t += 512)
        out[ATTN_OFF + (size_t)b * Tv + t] = __expf(s_scores[t] - Mg) * invL;
}

// ---------------- K2a: comb linear ----------------
__global__ void __launch_bounds__(256) k_comb(const int* __restrict__ tokens,
                                              const float* __restrict__ emb_table,
                                              const float* __restrict__ comb_W,
                                              const float* __restrict__ comb_b,
                                              const float* __restrict__ out) {
    __shared__ __align__(16) float xs[16][512];
    int tid = threadIdx.x, w = tid >> 5, lane = tid & 31;
    int b0 = blockIdx.y * 16;
    const float* ctx = out + CTX_OFF;

    for (int idx = tid; idx < 16 * 512; idx += 256) {
        int bb = idx >> 9, k = idx & 511;
        int gb = b0 + bb;
        float v;
        if (k < 256) {
            int tok = tokens[gb];
            v = emb_table[(size_t)tok * Hv + k];
        } else {
            v = ctx[gb * Hv + (k - 256)];
        }
        xs[bb][k] = v;
    }
    __syncthreads();

    int n = blockIdx.x * 8 + w;
    const float* wr = comb_W + (size_t)n * 512 + lane * 4;
    float4 w0 = *(const float4*)(wr);
    float4 w1 = *(const float4*)(wr + 128);
    float4 w2 = *(const float4*)(wr + 256);
    float4 w3 = *(const float4*)(wr + 384);
    float bvl = comb_b[n];

#pragma unroll 4
    for (int bb = 0; bb < 16; bb++) {
        const float* xr = &xs[bb][lane * 4];
        float4 x0 = *(const float4*)(xr);
        float4 x1 = *(const float4*)(xr + 128);
        float4 x2 = *(const float4*)(xr + 256);
        float4 x3 = *(const float4*)(xr + 384);
        float p = w0.x * x0.x + w0.y * x0.y + w0.z * x0.z + w0.w * x0.w
                + w1.x * x1.x + w1.y * x1.y + w1.z * x1.z + w1.w * x1.w
                + w2.x * x2.x + w2.y * x2.y + w2.z * x2.z + w2.w * x2.w
                + w3.x * x3.x + w3.y * x3.y + w3.z * x3.z + w3.w * x3.w;
#pragma unroll
        for (int o = 16; o; o >>= 1) p += __shfl_xor_sync(0xffffffffu, p, o);
        if (lane == 0) g_x[(b0 + bb) * Hv + n] = fmaxf(p + bvl, 0.f);
    }
}

// ---------------- K2b: gx and gh ----------------
__global__ void __launch_bounds__(256) k_gxgh(const float* __restrict__ hidden,
                                              const float* __restrict__ Wih,
                                              const float* __restrict__ Whh,
                                              const float* __restrict__ bih,
                                              const float* __restrict__ bhh) {
    __shared__ __align__(16) float xs[32][256];
    int tid = threadIdx.x, w = tid >> 5, lane = tid & 31;
    int b0 = blockIdx.y * 32;
    int z = blockIdx.z;
    const float* X = z ? hidden : g_x;
    const float* W = z ? Whh : Wih;
    const float* bias = z ? bhh : bih;
    float* Y = z ? g_gh : g_gx;

    for (int idx = tid; idx < 32 * 256; idx += 256)
        xs[idx >> 8][idx & 255] = X[(size_t)b0 * Hv + idx];
    __syncthreads();

    int n = blockIdx.x * 8 + w;
    const float* wr = W + (size_t)n * 256 + lane * 4;
    float4 w0 = *(const float4*)(wr);
    float4 w1 = *(const float4*)(wr + 128);
    float bvl = bias[n];

#pragma unroll 4
    for (int bb = 0; bb < 32; bb++) {
        const float* xr = &xs[bb][lane * 4];
        float4 x0 = *(const float4*)(xr);
        float4 x1 = *(const float4*)(xr + 128);
        float p = w0.x * x0.x + w0.y * x0.y + w0.z * x0.z + w0.w * x0.w
                + w1.x * x1.x + w1.y * x1.y + w1.z * x1.z + w1.w * x1.w;
#pragma unroll
        for (int o = 16; o; o >>= 1) p += __shfl_xor_sync(0xffffffffu, p, o);
        if (lane == 0) Y[(b0 + bb) * 768 + n] = p + bvl;
    }
}

// ---------------- K2c: GRU elementwise + h transpose ----------------
__global__ void k_gru(const float* __restrict__ hidden, float* __restrict__ out) {
    int b = blockIdx.x, h = threadIdx.x;
    float xr = g_gx[b * 768 + h],        hr = g_gh[b * 768 + h];
    float xz = g_gx[b * 768 + 256 + h],  hz = g_gh[b * 768 + 256 + h];
    float xn = g_gx[b * 768 + 512 + h],  hn = g_gh[b * 768 + 512 + h];
    float r = 1.f / (1.f + __expf(-(xr + hr)));
    float z = 1.f / (1.f + __expf(-(xz + hz)));
    float n = tanh_fast(xn + r * hn);
    float hprev = hidden[b * Hv + h];
    float hnew = (1.f - z) * n + z * hprev;
    out[HNEW_OFF + b * Hv + h] = hnew;
    g_ht[h * Bv + b] = hnew;
}

// ---------------- K3: logits GEMM via tf32 mma.sync ----------------
// block tile: 128 vocab x 128 batch, K=256 in chunks of 32.
// 8 warps: wm = wid&3 (32 v-rows), wn = wid>>2 (64 b-cols).
#define SW_STR 36     // s_w [128 v][36]
#define SH_STR 132    // s_h [32 k][132]
#define RES_STR 132   // res [64 b][132]
#define SW_SZ  (128 * SW_STR)          // 4608 words
#define SH_SZ  (32 * SH_STR)           // 4224 words
__global__ void __launch_bounds__(256, 2) k_logits(const float* __restrict__ Wv,
                                                   const float* __restrict__ out_b,
                                                   float* __restrict__ out) {
    __shared__ __align__(16) uint32_t smem[SW_SZ + SH_SZ];   // 35,328 B
    __shared__ __align__(16) float s_bias[128];
    uint32_t* s_w = smem;
    uint32_t* s_h = smem + SW_SZ;
    float* res = (float*)smem;   // epilogue reuse: 64*132 = 8448 words

    int tid = threadIdx.x, wid = tid >> 5, lane = tid & 31;
    int wm = wid & 3, wn = wid >> 2;
    int vb = blockIdx.x * 128;
    int lr = lane >> 2;       // 0..7
    int lc = lane & 3;        // 0..3

    if (tid < 128) s_bias[tid] = out_b[vb + tid];

    float acc[2][8][4];
#pragma unroll
    for (int mt = 0; mt < 2; mt++)
#pragma unroll
        for (int j = 0; j < 8; j++)
#pragma unroll
            for (int c = 0; c < 4; c++) acc[mt][j][c] = 0.f;

    for (int kc = 0; kc < 256; kc += 32) {
        __syncthreads();
        // load W chunk: [128 v][32 k] -> s_w[v][k]
        {
            int k4 = (tid & 7) * 4;
#pragma unroll
            for (int i = 0; i < 4; i++) {
                int v = (tid >> 3) + i * 32;
                float4 wv = *(const float4*)(Wv + (size_t)(vb + v) * 256 + kc + k4);
                uint32_t* d = s_w + v * SW_STR + k4;
                d[0] = to_tf32(wv.x); d[1] = to_tf32(wv.y);
                d[2] = to_tf32(wv.z); d[3] = to_tf32(wv.w);
            }
        }
        // load h chunk: [32 k][128 b] -> s_h[k][b]
        {
            int n4 = (tid & 31) * 4;
#pragma unroll
            for (int i = 0; i < 4; i++) {
                int k = (tid >> 5) + i * 8;
                float4 hv = *(const float4*)(g_ht + (size_t)(kc + k) * 128 + n4);
                uint32_t* d = s_h + k * SH_STR + n4;
                d[0] = to_tf32(hv.x); d[1] = to_tf32(hv.y);
                d[2] = to_tf32(hv.z); d[3] = to_tf32(hv.w);
            }
        }
        __syncthreads();

#pragma unroll
        for (int ks = 0; ks < 4; ks++) {
            int kk = ks * 8;
            uint32_t af[2][4];
#pragma unroll
            for (int mt = 0; mt < 2; mt++) {
                int row = wm * 32 + mt * 16 + lr;
                af[mt][0] = s_w[row * SW_STR + kk + lc];
                af[mt][1] = s_w[(row + 8) * SW_STR + kk + lc];
                af[mt][2] = s_w[row * SW_STR + kk + 4 + lc];
                af[mt][3] = s_w[(row + 8) * SW_STR + kk + 4 + lc];
            }
            uint32_t bf[8][2];
#pragma unroll
            for (int j = 0; j < 8; j++) {
                int n = wn * 64 + j * 8 + lr;
                bf[j][0] = s_h[(kk + lc) * SH_STR + n];
                bf[j][1] = s_h[(kk + 4 + lc) * SH_STR + n];
            }
#pragma unroll
            for (int mt = 0; mt < 2; mt++)
#pragma unroll
                for (int j = 0; j < 8; j++)
                    mma_tf32(acc[mt][j], af[mt][0], af[mt][1], af[mt][2], af[mt][3],
                             bf[j][0], bf[j][1]);
        }
    }

    // epilogue: two b-halves of 64, staged in smem (bias folded in)
    for (int h = 0; h < 2; h++) {
        __syncthreads();
        if (wn == h) {
#pragma unroll
            for (int mt = 0; mt < 2; mt++)
#pragma unroll
                for (int j = 0; j < 8; j++) {
                    int v0 = wm * 32 + mt * 16 + lr;
                    int b0 = j * 8 + lc * 2;
                    res[(b0    ) * RES_STR + v0    ] = acc[mt][j][0] + s_bias[v0];
                    res[(b0 + 1) * RES_STR + v0    ] = acc[mt][j][1] + s_bias[v0];
                    res[(b0    ) * RES_STR + v0 + 8] = acc[mt][j][2] + s_bias[v0 + 8];
                    res[(b0 + 1) * RES_STR + v0 + 8] = acc[mt][j][3] + s_bias[v0 + 8];
                }
        }
        __syncthreads();
        // coalesced writeout
#pragma unroll
        for (int i = 0; i < 32; i++) {
            int idx = i * 256 + tid;
            int bb = idx >> 7, v = idx & 127;
            out[(size_t)(h * 64 + bb) * Vv + vb + v] = res[bb * RES_STR + v];
        }
        // per-row softmax partials over this tile's 128 v
#pragma unroll
        for (int rr = 0; rr < 8; rr++) {
            int r = wid * 8 + rr;
            float4 x = *(const float4*)&res[r * RES_STR + lane * 4];
            float mx = fmaxf(fmaxf(x.x, x.y), fmaxf(x.z, x.w));
#pragma unroll
            for (int o = 16; o; o >>= 1) mx = fmaxf(mx, __shfl_xor_sync(0xffffffffu, mx, o));
            float se = __expf(x.x - mx) + __expf(x.y - mx) + __expf(x.z - mx) + __expf(x.w - mx);
#pragma unroll
            for (int o = 16; o; o >>= 1) se += __shfl_xor_sync(0xffffffffu, se, o);
            if (lane == 0) {
                int gb = h * 64 + r;
                g_pmax[blockIdx.x * Bv + gb] = mx;
                g_psum[blockIdx.x * Bv + gb] = se;
            }
        }
    }
}

// ---------------- K4: log_softmax finalize ----------------
__global__ void __launch_bounds__(512) k_lsm(float* __restrict__ out) {
    int b = blockIdx.x, tid = threadIdx.x, w = tid >> 5, lane = tid & 31;
    float m = NEG_HUGE, l = 0.f;
    for (int i = tid; i < NTILES; i += 512) {
        float mx = g_pmax[i * Bv + b];
        float se = g_psum[i * Bv + b];
        float nm = fmaxf(m, mx);
        l = l * __expf(m - nm) + se * __expf(mx - nm);
        m = nm;
    }
#pragma unroll
    for (int o = 16; o; o >>= 1) {
        float m2 = __shfl_xor_sync(0xffffffffu, m, o);
        float l2 = __shfl_xor_sync(0xffffffffu, l, o);
        float nm = fmaxf(m, m2);
        l = l * __expf(m - nm) + l2 * __expf(m2 - nm);
        m = nm;
    }
    __shared__ float sm[16], sl[16];
    if (lane == 0) { sm[w] = m; sl[w] = l; }
    __syncthreads();
    float M = NEG_HUGE;
#pragma unroll
    for (int i = 0; i < 16; i++) M = fmaxf(M, sm[i]);
    float L = 0.f;
#pragma unroll
    for (int i = 0; i < 16; i++) L += sl[i] * __expf(sm[i] - M);
    float lse = M + logf(L);

    float* row = out + (size_t)b * Vv;
    for (int v = tid; v < Vv; v += 512) row[v] -= lse;
}

// ---------------- launch ----------------
extern "C" void kernel_launch(void* const* d_in, const int* in_sizes, int n_in,
                              void* d_out, int out_size) {
    const int*   tokens    = (const int*)d_in[0];
    const float* hidden    = (const float*)d_in[1];
    const float* enc       = (const float*)d_in[2];
    const float* emb_table = (const float*)d_in[3];
    const float* attn_W    = (const float*)d_in[4];
    const float* attn_b    = (const float*)d_in[5];
    const float* comb_W    = (const float*)d_in[6];
    const float* comb_b    = (const float*)d_in[7];
    const float* gru_Wih   = (const float*)d_in[8];
    const float* gru_Whh   = (const float*)d_in[9];
    const float* gru_bih   = (const float*)d_in[10];
    const float* gru_bhh   = (const float*)d_in[11];
    const float* out_W     = (const float*)d_in[12];
    const float* out_b     = (const float*)d_in[13];
    float* out = (float*)d_out;

    k_attn<<<Bv, 512>>>(enc, attn_W, hidden, attn_b, out);
    k_comb<<<dim3(32, 8), 256>>>(tokens, emb_table, comb_W, comb_b, out);
    k_gxgh<<<dim3(96, 4, 2), 256>>>(hidden, gru_Wih, gru_Whh, gru_bih, gru_bhh);
    k_gru<<<Bv, 256>>>(hidden, out);
    k_logits<<<NTILES, 256>>>(out_W, out_b, out);
    k_lsm<<<Bv, 512>>>(out);
}